// round 16
// baseline (speedup 1.0000x reference)
#include <cuda_runtime.h>
#include <cuda_bf16.h>

#define NB     32
#define NZ     100
#define STATE  20
#define HIDN   128
#define HH     32
#define WW     32
#define STEPS  64
#define THRESH 0.1f

#define PIX    1024
#define IMG_SZ (STATE*PIX)
#define STATE_SZ (NB*IMG_SZ)
#define SPR    4
#define NSTRIP 128
#define TOTSTRIP 4096

// ---------------- persistent device scratch (ping-pong) ----------------
__device__ __align__(16) float g_T[2*STATE_SZ];
__device__ unsigned char      g_PM[2*TOTSTRIP];   // per-strip pre-mask byte
__device__ unsigned char      g_HT[2*TOTSTRIP];   // per-strip "T computed this step"
// packed weights (R1 layout)
__device__ __align__(16) float g_wp_pad [60*128*4];   // [cr][h][4] (kx 0..2)
__device__ __align__(16) float g_wu1_pad[32*128*4];   // [kg][h][4]

// ---------------- f32x2 helpers ----------------
__device__ __forceinline__ unsigned long long pack2(float v) {
    unsigned long long r; asm("mov.b64 %0, {%1, %1};" : "=l"(r) : "f"(v)); return r;
}
__device__ __forceinline__ void fma2(unsigned long long& d,
                                     unsigned long long a, unsigned long long b) {
    asm("fma.rn.f32x2 %0, %1, %2, %0;" : "+l"(d) : "l"(a), "l"(b));
}
__device__ __forceinline__ float2 unpack2(unsigned long long v) {
    float lo, hi; asm("mov.b64 {%0, %1}, %2;" : "=f"(lo), "=f"(hi) : "l"(v));
    return make_float2(lo, hi);
}

// ---------------- weight repack ----------------
__global__ void k_pack(const float* __restrict__ wp, const float* __restrict__ wu1)
{
    int i = blockIdx.x*256 + threadIdx.x;
    if (i < 128*180) {
        int h = i / 180, k = i % 180;            // k = c*9 + r*3 + kx
        g_wp_pad[(k/3)*512 + h*4 + (k%3)] = wp[i];
    }
    if (i < 128*128) {
        int h = i / 128, k = i % 128;
        g_wu1_pad[(k>>2)*512 + h*4 + (k&3)] = wu1[i];
    }
}

// ---------------- zero T buf0 + all flags (replay determinism) ----------------
__global__ void k_zero()
{
    int i = blockIdx.x*256 + threadIdx.x;
    if (i < STATE_SZ) g_T[i] = 0.f;
    if (i < 2*TOTSTRIP) { g_PM[i] = 0; g_HT[i] = 0; }
}

// ---------------- init MLP: z -> center pixel of T buf0 ----------------
__global__ void k_init(const float* __restrict__ z,
                       const float* __restrict__ w1, const float* __restrict__ b1,
                       const float* __restrict__ w2, const float* __restrict__ b2)
{
    int n = blockIdx.x;
    int t = threadIdx.x;  // 128 threads
    __shared__ float zz[NZ];
    __shared__ float h[50];
    if (t < NZ) zz[t] = z[n*NZ + t];
    __syncthreads();
    if (t < 50) {
        float a = b1[t];
        #pragma unroll 4
        for (int j = 0; j < NZ; j++) a += w1[t*NZ + j] * zz[j];
        h[t] = fmaxf(a, 0.f);
    }
    __syncthreads();
    const int ctr = 16*WW + 16;
    if (t < STATE-1) {
        float a = b2[t];
        #pragma unroll 5
        for (int j = 0; j < 50; j++) a += w2[t*50 + j] * h[j];
        g_T[n*IMG_SZ + (1+t)*PIX + ctr] = a;
    }
    if (t == STATE-1) {
        g_T[n*IMG_SZ + ctr] = 0.5f;
        g_PM[n*NSTRIP + 16*SPR + 2] = 0x01;      // center strip, pixel 0 (=col 16)
        g_HT[n*NSTRIP + 16*SPR + 2] = 1;
    }
}

// ---------------- fused step kernel: R15 structure + f32x2 core + MLP-batched weights ----------------
// grid: (ncols, nrows, 32); strip = (c_lo+bx, y_lo+by); block: 128 threads
__global__ void __launch_bounds__(128)
k_step(int step, int y_lo, int c_lo,
       const float* __restrict__ bp,
       const float* __restrict__ bu1,
       const float* __restrict__ wu2, const float* __restrict__ bu2)
{
    __shared__ __align__(16) float patchA[60*12];   // [c*3+r][col], cols x0-1..x0+8 (+pad)
    __shared__ __align__(16) float patchB[60*12];   // shifted by 1 col
    __shared__ __align__(16) float sperc[HIDN*8];   // [h][8]
    __shared__ __align__(16) float sh2T[8*132];     // [p][h] (+pad)
    __shared__ __align__(16) float tch0[5][12];
    __shared__ unsigned char s_pm[16], s_hot[16];
    __shared__ unsigned char aflag[3][10];
    __shared__ int sflag;

    const int in = step & 1;
    const float* __restrict__ Tin  = g_T + in*STATE_SZ;
    float*       __restrict__ Tout = g_T + (in^1)*STATE_SZ;
    const unsigned char* __restrict__ PMin  = g_PM + in*TOTSTRIP;
    unsigned char*       __restrict__ PMout = g_PM + (in^1)*TOTSTRIP;
    const unsigned char* __restrict__ HTin  = g_HT + in*TOTSTRIP;
    unsigned char*       __restrict__ HTout = g_HT + (in^1)*TOTSTRIP;

    const int sx = c_lo + blockIdx.x;
    const int x0 = sx * 8;
    const int y  = y_lo + blockIdx.y;
    const int n  = blockIdx.z;
    const int t  = threadIdx.x;
    const int se = n*NSTRIP + y*SPR + sx;
    const int first = (step == 0);

    // ---- gate: any pre pixel in rows y-2..y+2, cols x0-2..x0+9 ----
    if (t < 32) {
        int h1 = 0;
        if (t < 15) {
            int dy = t/3 - 2, ds = t%3 - 1;
            int yy = y + dy, ss = sx + ds;
            unsigned pm = 0, ht = 0;
            if ((unsigned)yy < (unsigned)HH && (unsigned)ss < (unsigned)SPR) {
                pm = PMin[n*NSTRIP + yy*SPR + ss];
                ht = HTin[n*NSTRIP + yy*SPR + ss];
            }
            s_pm[t]  = (unsigned char)pm;
            s_hot[t] = (unsigned char)ht;
            unsigned cm = (ds == 0) ? 0xFFu : (ds < 0 ? 0xC0u : 0x03u);
            h1 = (pm & cm) != 0;
        }
        h1 = __any_sync(0xffffffffu, h1);
        if (t == 0) {
            sflag = h1;
            HTout[se] = (unsigned char)h1;
            if (!h1) PMout[se] = 0;    // cold: kill stale parity flags
        }
    }
    __syncthreads();
    if (!sflag) return;

    // ---- stage T_in ch0 5x12, gated by HOT_in of covering strip ----
    if (t < 60) {
        int rr = t / 12, cc = t % 12;
        int yy = y - 2 + rr, xx = x0 - 2 + cc;
        float v = 0.f;
        if ((unsigned)yy < (unsigned)HH && (unsigned)xx < (unsigned)WW) {
            int hidx = rr*3 + ((xx >> 3) - sx + 1);
            if (s_hot[hidx]) v = Tin[n*IMG_SZ + yy*WW + xx];
        }
        tch0[rr][cc] = v;
    }
    __syncthreads();

    // ---- alive flags for 3x10 halo: PMbit ∧ maxpool3(T ch0) > θ ----
    if (t < 30) {
        int r = t / 10, col = t % 10;
        int yy = y - 1 + r, xx = x0 - 1 + col;
        int f = 0;
        if ((unsigned)yy < (unsigned)HH && (unsigned)xx < (unsigned)WW) {
            int pidx = (r + 1)*3 + ((xx >> 3) - sx + 1);
            if ((s_pm[pidx] >> (xx & 7)) & 1) {
                if (first) f = 1;
                else {
                    float m = -1.f;
                    #pragma unroll
                    for (int dr = 0; dr < 3; dr++)
                        #pragma unroll
                        for (int dc = 0; dc < 3; dc++)
                            m = fmaxf(m, tch0[r + dr][col + dc]);
                    f = (m > THRESH) ? 1 : 0;
                }
            }
        }
        aflag[r][col] = (unsigned char)f;
    }
    __syncthreads();

    // ---- build patchA/patchB = masked S over [20][3][12] ----
    for (int i = t; i < STATE*3*12; i += 128) {
        int row = i / 12, col = i - row*12;      // row = c*3 + r
        int r = row % 3;
        float v = 0.f;
        if (col < 10 && aflag[r][col]) {
            int c = row / 3;
            int yy = y - 1 + r, xx = x0 - 1 + col;
            v = Tin[n*IMG_SZ + c*PIX + yy*WW + xx];
        }
        patchA[i] = v;
        if (col >= 1) patchB[i - 1] = v;
        else          patchB[row*12 + 11] = 0.f;
    }
    __syncthreads();

    // ---- pre-mask for own 8 pixels -> PM_out byte ----
    if (t < 32) {
        int pre = 0;
        if (t < 8) {
            float m = 0.f;
            #pragma unroll
            for (int r = 0; r < 3; r++)
                #pragma unroll
                for (int cc = 0; cc < 3; cc++)
                    m = fmaxf(m, patchA[r*12 + t + cc]);
            pre = (m > THRESH) ? 1 : 0;
        }
        unsigned bal = __ballot_sync(0xffffffffu, pre);
        if (t == 0) PMout[se] = (unsigned char)(bal & 0xFF);
    }

    // ---- perceive: 3x3 conv 20->128, f32x2, 6-wide weight preload ----
    const float4* __restrict__ wp4 = (const float4*)g_wp_pad;
    unsigned long long acc[4];
    {
        unsigned long long b2v = pack2(__ldg(&bp[t]));
        acc[0] = b2v; acc[1] = b2v; acc[2] = b2v; acc[3] = b2v;
    }
    #pragma unroll
    for (int cb = 0; cb < 60; cb += 6) {
        float4 wreg[6];
        #pragma unroll
        for (int j = 0; j < 6; j++)
            wreg[j] = __ldg(&wp4[(cb + j)*128 + t]);
        #pragma unroll
        for (int j = 0; j < 6; j++) {
            const int cr = cb + j;
            const ulonglong2 pa0 = *(const ulonglong2*)&patchA[cr*12 + 0];
            const ulonglong2 pa1 = *(const ulonglong2*)&patchA[cr*12 + 4];
            const unsigned long long d8 = *(const unsigned long long*)&patchA[cr*12 + 8];
            const ulonglong2 pb0 = *(const ulonglong2*)&patchB[cr*12 + 0];
            const ulonglong2 pb1 = *(const ulonglong2*)&patchB[cr*12 + 4];
            const unsigned long long W0 = pack2(wreg[j].x);
            const unsigned long long W1 = pack2(wreg[j].y);
            const unsigned long long W2 = pack2(wreg[j].z);
            fma2(acc[0], W0, pa0.x); fma2(acc[1], W0, pa0.y);
            fma2(acc[2], W0, pa1.x); fma2(acc[3], W0, pa1.y);
            fma2(acc[0], W1, pb0.x); fma2(acc[1], W1, pb0.y);
            fma2(acc[2], W1, pb1.x); fma2(acc[3], W1, pb1.y);
            fma2(acc[0], W2, pa0.y); fma2(acc[1], W2, pa1.x);
            fma2(acc[2], W2, pa1.y); fma2(acc[3], W2, d8);
        }
    }
    {
        unsigned long long* sp = (unsigned long long*)sperc;
        sp[t*4 + 0] = acc[0]; sp[t*4 + 1] = acc[1];
        sp[t*4 + 2] = acc[2]; sp[t*4 + 3] = acc[3];
    }
    __syncthreads();

    // ---- up1: 1x1 128->128 + relu, f32x2, 4-wide weight preload ----
    unsigned long long a1[4];
    {
        unsigned long long b2v = pack2(__ldg(&bu1[t]));
        a1[0] = b2v; a1[1] = b2v; a1[2] = b2v; a1[3] = b2v;
    }
    const float4* __restrict__ wu14 = (const float4*)g_wu1_pad;
    #pragma unroll
    for (int kb = 0; kb < 32; kb += 4) {
        float4 wreg[4];
        #pragma unroll
        for (int m = 0; m < 4; m++)
            wreg[m] = __ldg(&wu14[(kb + m)*128 + t]);
        #pragma unroll
        for (int m = 0; m < 4; m++) {
            const float wk[4] = {wreg[m].x, wreg[m].y, wreg[m].z, wreg[m].w};
            #pragma unroll
            for (int j = 0; j < 4; j++) {
                const int k = (kb + m)*4 + j;
                const unsigned long long W = pack2(wk[j]);
                const ulonglong2 v0 = *(const ulonglong2*)&sperc[k*8 + 0];
                const ulonglong2 v1 = *(const ulonglong2*)&sperc[k*8 + 4];
                fma2(a1[0], W, v0.x); fma2(a1[1], W, v0.y);
                fma2(a1[2], W, v1.x); fma2(a1[3], W, v1.y);
            }
        }
    }
    #pragma unroll
    for (int j = 0; j < 4; j++) {
        float2 v = unpack2(a1[j]);
        sh2T[(2*j+0)*132 + t] = fmaxf(v.x, 0.f);
        sh2T[(2*j+1)*132 + t] = fmaxf(v.y, 0.f);
    }
    __syncthreads();

    // ---- up2: 1x1 128->20, T_out = maskedS + upd (160 outputs, f32x2) ----
    #pragma unroll
    for (int round = 0; round < 2; round++) {
        int i2 = t + round*128;
        if (i2 < 160) {
            int c = i2 >> 3, p = i2 & 7;
            unsigned long long A0 = 0ull, A1 = 0ull;
            const ulonglong2* hv = (const ulonglong2*)&sh2T[p*132];
            const ulonglong2* wv = (const ulonglong2*)&wu2[c*128];
            #pragma unroll 8
            for (int k4 = 0; k4 < 32; k4++) {
                const ulonglong2 h2 = hv[k4];
                const ulonglong2 w2 = __ldg(&wv[k4]);
                fma2(A0, w2.x, h2.x);
                fma2(A1, w2.y, h2.y);
            }
            float2 s0 = unpack2(A0), s1 = unpack2(A1);
            float a = __ldg(&bu2[c]) + ((s0.x + s0.y) + (s1.x + s1.y));
            Tout[n*IMG_SZ + c*PIX + y*WW + x0 + p] = patchA[(c*3+1)*12 + p + 1] + a;
        }
    }
}

// ---------------- extract: reconstruct masked ch0 (final parity = 0) ----------------
__global__ void k_extract(float* __restrict__ out)
{
    int gg = blockIdx.x*256 + threadIdx.x;     // 0..32767
    int n = gg >> 10, rem = gg & 1023;
    int y = rem >> 5, x = rem & 31;

    float v = 0.f;
    unsigned pm = g_PM[n*NSTRIP + y*SPR + (x >> 3)];
    if ((pm >> (x & 7)) & 1) {
        const float* __restrict__ Tn = g_T + n*IMG_SZ;
        float m = -1.f;
        #pragma unroll
        for (int dy = -1; dy <= 1; dy++) {
            int yy = y + dy;
            if ((unsigned)yy >= (unsigned)HH) continue;
            #pragma unroll
            for (int dx = -1; dx <= 1; dx++) {
                int xx = x + dx;
                if ((unsigned)xx >= (unsigned)WW) continue;
                if (g_HT[n*NSTRIP + yy*SPR + (xx >> 3)])
                    m = fmaxf(m, Tn[yy*WW + xx]);
            }
        }
        if (m > THRESH) v = Tn[rem];
    }
    out[gg] = v;
}

// ---------------- launch ----------------
extern "C" void kernel_launch(void* const* d_in, const int* in_sizes, int n_in,
                              void* d_out, int out_size)
{
    const float* z   = (const float*)d_in[0];
    const float* w1  = (const float*)d_in[1];
    const float* b1  = (const float*)d_in[2];
    const float* w2  = (const float*)d_in[3];
    const float* b2  = (const float*)d_in[4];
    const float* wp  = (const float*)d_in[5];
    const float* bp  = (const float*)d_in[6];
    const float* wu1 = (const float*)d_in[7];
    const float* bu1 = (const float*)d_in[8];
    const float* wu2 = (const float*)d_in[9];
    const float* bu2 = (const float*)d_in[10];
    float* out = (float*)d_out;

    k_pack<<<(128*180 + 255)/256, 256>>>(wp, wu1);
    k_zero<<<(STATE_SZ + 255)/256, 256>>>();
    k_init<<<NB, 128>>>(z, w1, b1, w2, b2);

    for (int s = 0; s < STEPS; s++) {
        int R = s + 1;
        int y_lo = 16 - R - 2; if (y_lo < 0) y_lo = 0;
        int y_hi = 16 + R + 2; if (y_hi > 31) y_hi = 31;
        int nrows = y_hi - y_lo + 1;
        int c_lo = 0;
        while (c_lo < 3 && 8*c_lo + 9 < 16 - R) c_lo++;
        int c_hi = 3;
        while (c_hi > 0 && 8*c_hi - 2 > 16 + R) c_hi--;
        int ncols = c_hi - c_lo + 1;
        k_step<<<dim3(ncols, nrows, NB), 128>>>(s, y_lo, c_lo, bp, bu1, wu2, bu2);
    }
    k_extract<<<(NB*PIX)/256, 256>>>(out);
}

// round 17
// speedup vs baseline: 1.2453x; 1.2453x over previous
#include <cuda_runtime.h>
#include <cuda_bf16.h>

#define NB     32
#define NZ     100
#define STATE  20
#define HIDN   128
#define HH     32
#define WW     32
#define STEPS  64
#define THRESH 0.1f

#define PIX    1024
#define IMG_SZ (STATE*PIX)
#define STATE_SZ (NB*IMG_SZ)
#define SPR    4
#define NSTRIP 128
#define TOTSTRIP 4096

// ---------------- persistent device scratch (ping-pong) ----------------
__device__ __align__(16) float g_T[2*STATE_SZ];
// fused flags: low byte = PM (pre-mask bits), high byte = HT (computed this step)
__device__ unsigned short     g_F[2][TOTSTRIP];
// packed weights (R1 layout)
__device__ __align__(16) float g_wp_pad [60*128*4];   // [cr][h][4] (kx 0..2)
__device__ __align__(16) float g_wu1_pad[32*128*4];   // [kg][h][4]

// ---------------- weight repack ----------------
__global__ void k_pack(const float* __restrict__ wp, const float* __restrict__ wu1)
{
    int i = blockIdx.x*256 + threadIdx.x;
    if (i < 128*180) {
        int h = i / 180, k = i % 180;            // k = c*9 + r*3 + kx
        g_wp_pad[(k/3)*512 + h*4 + (k%3)] = wp[i];
    }
    if (i < 128*128) {
        int h = i / 128, k = i % 128;
        g_wu1_pad[(k>>2)*512 + h*4 + (k&3)] = wu1[i];
    }
}

// ---------------- zero T buf0 + all flags (replay determinism) ----------------
__global__ void k_zero()
{
    int i = blockIdx.x*256 + threadIdx.x;
    if (i < STATE_SZ) g_T[i] = 0.f;
    if (i < 2*TOTSTRIP) ((unsigned short*)g_F)[i] = 0;
}

// ---------------- init MLP: z -> center pixel of T buf0 ----------------
__global__ void k_init(const float* __restrict__ z,
                       const float* __restrict__ w1, const float* __restrict__ b1,
                       const float* __restrict__ w2, const float* __restrict__ b2)
{
    int n = blockIdx.x;
    int t = threadIdx.x;  // 128 threads
    __shared__ float zz[NZ];
    __shared__ float h[50];
    if (t < NZ) zz[t] = z[n*NZ + t];
    __syncthreads();
    if (t < 50) {
        float a = b1[t];
        #pragma unroll 4
        for (int j = 0; j < NZ; j++) a += w1[t*NZ + j] * zz[j];
        h[t] = fmaxf(a, 0.f);
    }
    __syncthreads();
    const int ctr = 16*WW + 16;
    if (t < STATE-1) {
        float a = b2[t];
        #pragma unroll 5
        for (int j = 0; j < 50; j++) a += w2[t*50 + j] * h[j];
        g_T[n*IMG_SZ + (1+t)*PIX + ctr] = a;
    }
    if (t == STATE-1) {
        g_T[n*IMG_SZ + ctr] = 0.5f;
        g_F[0][n*NSTRIP + 16*SPR + 2] = (unsigned short)((1u << 8) | 0x01u);
    }
}

// ---------------- fused step kernel: R13 core + entry prefetch + fused flags ----------------
// grid: (ncols, nrows, 32); strip = (c_lo+bx, y_lo+by); block: 128 threads
__global__ void __launch_bounds__(128)
k_step(int step, int y_lo, int c_lo,
       const float* __restrict__ bp,
       const float* __restrict__ bu1,
       const float* __restrict__ wu2, const float* __restrict__ bu2)
{
    __shared__ __align__(16) float patch[STATE][3][12];
    __shared__ __align__(16) float s_perc[HIDN][8];
    __shared__ __align__(16) float s_h2 [HIDN][8];
    __shared__ __align__(16) float tch0[5][12];
    __shared__ unsigned char s_pm[16], s_hot[16];
    __shared__ unsigned char aflag[3][10];
    __shared__ int sflag;

    const int in = step & 1;
    const float* __restrict__ Tin  = g_T + in*STATE_SZ;
    float*       __restrict__ Tout = g_T + (in^1)*STATE_SZ;

    const int sx = c_lo + blockIdx.x;
    const int x0 = sx * 8;
    const int y  = y_lo + blockIdx.y;
    const int n  = blockIdx.z;
    const int t  = threadIdx.x;
    const int se = n*NSTRIP + y*SPR + sx;
    const int first = (step == 0);

    // ===== entry prefetch: state-independent loads, overlap the whole gate/patch prefix =====
    const float4* __restrict__ wp4  = (const float4*)g_wp_pad;
    const float4* __restrict__ wu14 = (const float4*)g_wu1_pad;
    float bias_p  = __ldg(&bp[t]);
    float bias_u1 = __ldg(&bu1[t]);
    float4 wpre[6];
    #pragma unroll
    for (int j = 0; j < 6; j++) wpre[j] = __ldg(&wp4[j*128 + t]);
    float4 wu1pre[4];
    #pragma unroll
    for (int j = 0; j < 4; j++) wu1pre[j] = __ldg(&wu14[j*128 + t]);

    // ---- gate: any pre pixel in rows y-2..y+2, cols x0-2..x0+9 (single fused LDG) ----
    if (t < 32) {
        int h1 = 0;
        if (t < 15) {
            int dy = t/3 - 2, ds = t%3 - 1;
            int yy = y + dy, ss = sx + ds;
            unsigned w = 0;
            if ((unsigned)yy < (unsigned)HH && (unsigned)ss < (unsigned)SPR)
                w = g_F[in][n*NSTRIP + yy*SPR + ss];
            s_pm[t]  = (unsigned char)(w & 0xFFu);
            s_hot[t] = (unsigned char)(w >> 8);
            unsigned cm = (ds == 0) ? 0xFFu : (ds < 0 ? 0xC0u : 0x03u);
            h1 = (w & cm) != 0;
        }
        h1 = __any_sync(0xffffffffu, h1);
        if (t == 0) {
            sflag = h1;
            unsigned char* Fo = (unsigned char*)&g_F[in^1][se];
            Fo[1] = (unsigned char)h1;       // HT_out
            if (!h1) Fo[0] = 0;              // cold: kill stale PM
        }
    }
    __syncthreads();
    if (!sflag) return;

    // ---- stage T_in ch0 5x12, gated by HOT_in of covering strip ----
    if (t < 60) {
        int rr = t / 12, cc = t % 12;
        int yy = y - 2 + rr, xx = x0 - 2 + cc;
        float v = 0.f;
        if ((unsigned)yy < (unsigned)HH && (unsigned)xx < (unsigned)WW) {
            int hidx = rr*3 + ((xx >> 3) - sx + 1);
            if (s_hot[hidx]) v = Tin[n*IMG_SZ + yy*WW + xx];
        }
        tch0[rr][cc] = v;
    }
    __syncthreads();

    // ---- alive flags for 3x10 halo: PMbit ∧ maxpool3(T ch0) > θ ----
    if (t < 30) {
        int r = t / 10, col = t % 10;
        int yy = y - 1 + r, xx = x0 - 1 + col;
        int f = 0;
        if ((unsigned)yy < (unsigned)HH && (unsigned)xx < (unsigned)WW) {
            int pidx = (r + 1)*3 + ((xx >> 3) - sx + 1);
            if ((s_pm[pidx] >> (xx & 7)) & 1) {
                if (first) f = 1;
                else {
                    float m = -1.f;
                    #pragma unroll
                    for (int dr = 0; dr < 3; dr++)
                        #pragma unroll
                        for (int dc = 0; dc < 3; dc++)
                            m = fmaxf(m, tch0[r + dr][col + dc]);
                    f = (m > THRESH) ? 1 : 0;
                }
            }
        }
        aflag[r][col] = (unsigned char)f;
    }
    __syncthreads();

    // ---- build patch = masked S over [20][3][12] ----
    for (int i = t; i < STATE*3*12; i += 128) {
        int c = i / 36, rem = i - c*36, r = rem / 12, col = rem - r*12;
        float v = 0.f;
        if (col < 10 && aflag[r][col]) {
            int yy = y - 1 + r, xx = x0 - 1 + col;
            v = Tin[n*IMG_SZ + c*PIX + yy*WW + xx];
        }
        patch[c][r][col] = v;
    }
    __syncthreads();

    // ---- pre-mask for own 8 pixels -> PM_out byte ----
    if (t < 32) {
        int pre = 0;
        if (t < 8) {
            float m = 0.f;
            #pragma unroll
            for (int r = 0; r < 3; r++)
                #pragma unroll
                for (int cc = 0; cc < 3; cc++)
                    m = fmaxf(m, patch[0][r][t + cc]);
            pre = (m > THRESH) ? 1 : 0;
        }
        unsigned bal = __ballot_sync(0xffffffffu, pre);
        if (t == 0)
            ((unsigned char*)&g_F[in^1][se])[0] = (unsigned char)(bal & 0xFF);
    }

    // ---- perceive: 3x3 conv 20->128, scalar core, batched weights ----
    float acc[8];
    #pragma unroll
    for (int p = 0; p < 8; p++) acc[p] = bias_p;

    // rows 0..5 from entry prefetch
    #pragma unroll
    for (int j = 0; j < 6; j++) {
        const int cr = j;
        const float4 a = *(const float4*)&patch[0][0][cr*12 + 0];
        const float4 b = *(const float4*)&patch[0][0][cr*12 + 4];
        const float4 d = *(const float4*)&patch[0][0][cr*12 + 8];
        float rv[12] = {a.x,a.y,a.z,a.w, b.x,b.y,b.z,b.w, d.x,d.y,d.z,d.w};
        float wk[3] = {wpre[j].x, wpre[j].y, wpre[j].z};
        #pragma unroll
        for (int kx = 0; kx < 3; kx++)
            #pragma unroll
            for (int p = 0; p < 8; p++)
                acc[p] = fmaf(wk[kx], rv[p + kx], acc[p]);
    }
    // rows 6..59 in 6-wide batches
    #pragma unroll 1
    for (int cb = 6; cb < 60; cb += 6) {
        float4 wreg[6];
        #pragma unroll
        for (int j = 0; j < 6; j++)
            wreg[j] = __ldg(&wp4[(cb + j)*128 + t]);
        #pragma unroll
        for (int j = 0; j < 6; j++) {
            const int cr = cb + j;
            const float4 a = *(const float4*)&patch[0][0][cr*12 + 0];
            const float4 b = *(const float4*)&patch[0][0][cr*12 + 4];
            const float4 d = *(const float4*)&patch[0][0][cr*12 + 8];
            float rv[12] = {a.x,a.y,a.z,a.w, b.x,b.y,b.z,b.w, d.x,d.y,d.z,d.w};
            float wk[3] = {wreg[j].x, wreg[j].y, wreg[j].z};
            #pragma unroll
            for (int kx = 0; kx < 3; kx++)
                #pragma unroll
                for (int p = 0; p < 8; p++)
                    acc[p] = fmaf(wk[kx], rv[p + kx], acc[p]);
        }
    }
    #pragma unroll
    for (int p = 0; p < 8; p++) s_perc[t][p] = acc[p];
    __syncthreads();

    // ---- up1: 1x1 128->128 + ReLU, scalar core, batched weights ----
    float acc2[8];
    #pragma unroll
    for (int p = 0; p < 8; p++) acc2[p] = bias_u1;

    // kg 0..3 from entry prefetch
    #pragma unroll
    for (int m = 0; m < 4; m++) {
        float wk[4] = {wu1pre[m].x, wu1pre[m].y, wu1pre[m].z, wu1pre[m].w};
        #pragma unroll
        for (int j = 0; j < 4; j++) {
            int k = m*4 + j;
            const float4 va = *(const float4*)&s_perc[k][0];
            const float4 vb = *(const float4*)&s_perc[k][4];
            acc2[0] = fmaf(wk[j], va.x, acc2[0]);
            acc2[1] = fmaf(wk[j], va.y, acc2[1]);
            acc2[2] = fmaf(wk[j], va.z, acc2[2]);
            acc2[3] = fmaf(wk[j], va.w, acc2[3]);
            acc2[4] = fmaf(wk[j], vb.x, acc2[4]);
            acc2[5] = fmaf(wk[j], vb.y, acc2[5]);
            acc2[6] = fmaf(wk[j], vb.z, acc2[6]);
            acc2[7] = fmaf(wk[j], vb.w, acc2[7]);
        }
    }
    #pragma unroll 1
    for (int kb = 4; kb < 32; kb += 4) {
        float4 wreg[4];
        #pragma unroll
        for (int m = 0; m < 4; m++)
            wreg[m] = __ldg(&wu14[(kb + m)*128 + t]);
        #pragma unroll
        for (int m = 0; m < 4; m++) {
            float wk[4] = {wreg[m].x, wreg[m].y, wreg[m].z, wreg[m].w};
            #pragma unroll
            for (int j = 0; j < 4; j++) {
                int k = (kb + m)*4 + j;
                const float4 va = *(const float4*)&s_perc[k][0];
                const float4 vb = *(const float4*)&s_perc[k][4];
                acc2[0] = fmaf(wk[j], va.x, acc2[0]);
                acc2[1] = fmaf(wk[j], va.y, acc2[1]);
                acc2[2] = fmaf(wk[j], va.z, acc2[2]);
                acc2[3] = fmaf(wk[j], va.w, acc2[3]);
                acc2[4] = fmaf(wk[j], vb.x, acc2[4]);
                acc2[5] = fmaf(wk[j], vb.y, acc2[5]);
                acc2[6] = fmaf(wk[j], vb.z, acc2[6]);
                acc2[7] = fmaf(wk[j], vb.w, acc2[7]);
            }
        }
    }
    #pragma unroll
    for (int p = 0; p < 8; p++) s_h2[t][p] = fmaxf(acc2[p], 0.f);
    __syncthreads();

    // ---- up2: 1x1 128->20, T_out = maskedS + upd (R1 verbatim) ----
    {
        int c = t >> 3, p = t & 7;
        float a = __ldg(&bu2[c]);
        #pragma unroll 8
        for (int k4 = 0; k4 < 32; k4++) {
            const float4 w4 = __ldg((const float4*)&wu2[c*128 + k4*4]);
            a = fmaf(w4.x, s_h2[k4*4+0][p], a);
            a = fmaf(w4.y, s_h2[k4*4+1][p], a);
            a = fmaf(w4.z, s_h2[k4*4+2][p], a);
            a = fmaf(w4.w, s_h2[k4*4+3][p], a);
        }
        Tout[n*IMG_SZ + c*PIX + y*WW + x0 + p] = patch[c][1][p+1] + a;
    }
    if (t < 32) {
        int i = t + 128;
        int c = i >> 3, p = i & 7;
        float a = __ldg(&bu2[c]);
        #pragma unroll 8
        for (int k4 = 0; k4 < 32; k4++) {
            const float4 w4 = __ldg((const float4*)&wu2[c*128 + k4*4]);
            a = fmaf(w4.x, s_h2[k4*4+0][p], a);
            a = fmaf(w4.y, s_h2[k4*4+1][p], a);
            a = fmaf(w4.z, s_h2[k4*4+2][p], a);
            a = fmaf(w4.w, s_h2[k4*4+3][p], a);
        }
        Tout[n*IMG_SZ + c*PIX + y*WW + x0 + p] = patch[c][1][p+1] + a;
    }
}

// ---------------- extract: reconstruct masked ch0 (final parity = 0) ----------------
__global__ void k_extract(float* __restrict__ out)
{
    int gg = blockIdx.x*256 + threadIdx.x;     // 0..32767
    int n = gg >> 10, rem = gg & 1023;
    int y = rem >> 5, x = rem & 31;

    float v = 0.f;
    unsigned pm = g_F[0][n*NSTRIP + y*SPR + (x >> 3)] & 0xFFu;
    if ((pm >> (x & 7)) & 1) {
        const float* __restrict__ Tn = g_T + n*IMG_SZ;
        float m = -1.f;
        #pragma unroll
        for (int dy = -1; dy <= 1; dy++) {
            int yy = y + dy;
            if ((unsigned)yy >= (unsigned)HH) continue;
            #pragma unroll
            for (int dx = -1; dx <= 1; dx++) {
                int xx = x + dx;
                if ((unsigned)xx >= (unsigned)WW) continue;
                if (g_F[0][n*NSTRIP + yy*SPR + (xx >> 3)] >> 8)
                    m = fmaxf(m, Tn[yy*WW + xx]);
            }
        }
        if (m > THRESH) v = Tn[rem];
    }
    out[gg] = v;
}

// ---------------- launch ----------------
extern "C" void kernel_launch(void* const* d_in, const int* in_sizes, int n_in,
                              void* d_out, int out_size)
{
    const float* z   = (const float*)d_in[0];
    const float* w1  = (const float*)d_in[1];
    const float* b1  = (const float*)d_in[2];
    const float* w2  = (const float*)d_in[3];
    const float* b2  = (const float*)d_in[4];
    const float* wp  = (const float*)d_in[5];
    const float* bp  = (const float*)d_in[6];
    const float* wu1 = (const float*)d_in[7];
    const float* bu1 = (const float*)d_in[8];
    const float* wu2 = (const float*)d_in[9];
    const float* bu2 = (const float*)d_in[10];
    float* out = (float*)d_out;

    k_pack<<<(128*180 + 255)/256, 256>>>(wp, wu1);
    k_zero<<<(STATE_SZ + 255)/256, 256>>>();
    k_init<<<NB, 128>>>(z, w1, b1, w2, b2);

    for (int s = 0; s < STEPS; s++) {
        int R = s + 1;
        int y_lo = 16 - R - 2; if (y_lo < 0) y_lo = 0;
        int y_hi = 16 + R + 2; if (y_hi > 31) y_hi = 31;
        int nrows = y_hi - y_lo + 1;
        int c_lo = 0;
        while (c_lo < 3 && 8*c_lo + 9 < 16 - R) c_lo++;
        int c_hi = 3;
        while (c_hi > 0 && 8*c_hi - 2 > 16 + R) c_hi--;
        int ncols = c_hi - c_lo + 1;
        k_step<<<dim3(ncols, nrows, NB), 128>>>(s, y_lo, c_lo, bp, bu1, wu2, bu2);
    }
    k_extract<<<(NB*PIX)/256, 256>>>(out);
}